// round 8
// baseline (speedup 1.0000x reference)
#include <cuda_runtime.h>
#include <math.h>
#include <mma.h>

using namespace nvcuda;

#define N_NODES 50000
#define F_IN    128
#define H1      128
#define H2      64
#define E_TRAIN 600000
#define E_SCORE 200000
#define NB_SCAN 196                     // ceil(50000/256)

// Scratch buffers (device globals — no allocation allowed)
__device__ float g_dinv  [N_NODES];
__device__ int   g_cnt   [N_NODES];         // in-degree (no self-loop)
__device__ int   g_rowptr[N_NODES + 1];     // CSR row pointers (by dst)
__device__ int   g_cursor[N_NODES];         // fill cursors
__device__ int   g_bsum  [256];             // scan block sums
__device__ int   g_boff  [256];             // scanned block offsets
__device__ int   g_esrc  [E_TRAIN];         // dst-sorted source indices
__device__ float g_h0    [N_NODES * H1];    // x @ W1
__device__ float g_agg1  [N_NODES * H1];    // layer-1 aggregated (pre-relu)
__device__ float g_h2p   [N_NODES * H2];    // relu(agg1) @ W2
__device__ float g_agg2  [N_NODES * H2];    // layer-2 output h2

// ---------------------------------------------------------------- degree/CSR build
__global__ void k_zero_cnt() {
    int i = blockIdx.x * blockDim.x + threadIdx.x;
    if (i < N_NODES) g_cnt[i] = 0;
}

__global__ void k_count(const int* __restrict__ ei) {
    int e = blockIdx.x * blockDim.x + threadIdx.x;
    if (e < E_TRAIN) atomicAdd(&g_cnt[ei[E_TRAIN + e]], 1);   // col = target
}

// Shuffle-based block scan; also emits dinv (fused, saves a launch).
__global__ void k_scan1() {
    __shared__ int wsum[8];
    int t = threadIdx.x;
    int i = blockIdx.x * 256 + t;
    int v = (i < N_NODES) ? g_cnt[i] : 0;
    int s = v;
#pragma unroll
    for (int o = 1; o < 32; o <<= 1) {
        int u = __shfl_up_sync(0xFFFFFFFFu, s, o);
        if ((t & 31) >= o) s += u;
    }
    if ((t & 31) == 31) wsum[t >> 5] = s;
    __syncthreads();
    if (t < 8) {
        int w = wsum[t];
        int e = w;
#pragma unroll
        for (int o = 1; o < 8; o <<= 1) {
            int u = __shfl_up_sync(0xFFu, e, o);
            if (t >= o) e += u;
        }
        wsum[t] = e - w;               // exclusive warp offset
    }
    __syncthreads();
    int incl = s + wsum[t >> 5];
    if (i < N_NODES) {
        g_rowptr[i] = incl - v;        // exclusive
        g_dinv[i]   = rsqrtf((float)(v + 1));
    }
    if (t == 255) g_bsum[blockIdx.x] = incl;
}

__global__ void k_scan2() {
    __shared__ int wsum[8];
    int t = threadIdx.x;
    int v = (t < NB_SCAN) ? g_bsum[t] : 0;
    int s = v;
#pragma unroll
    for (int o = 1; o < 32; o <<= 1) {
        int u = __shfl_up_sync(0xFFFFFFFFu, s, o);
        if ((t & 31) >= o) s += u;
    }
    if ((t & 31) == 31) wsum[t >> 5] = s;
    __syncthreads();
    if (t < 8) {
        int w = wsum[t];
        int e = w;
#pragma unroll
        for (int o = 1; o < 8; o <<= 1) {
            int u = __shfl_up_sync(0xFFu, e, o);
            if (t >= o) e += u;
        }
        wsum[t] = e - w;
    }
    __syncthreads();
    g_boff[t] = s + wsum[t >> 5] - v;  // exclusive
}

__global__ void k_scan3() {
    int i = blockIdx.x * blockDim.x + threadIdx.x;
    if (i < N_NODES) {
        int r = g_rowptr[i] + g_boff[i >> 8];
        g_rowptr[i] = r;
        g_cursor[i] = r;
    }
    if (i == 0) g_rowptr[N_NODES] = E_TRAIN;
}

__global__ void k_fill(const int* __restrict__ ei) {
    int e = blockIdx.x * blockDim.x + threadIdx.x;
    if (e >= E_TRAIN) return;
    int dst = ei[E_TRAIN + e];
    int p = atomicAdd(&g_cursor[dst], 1);
    g_esrc[p] = ei[e];
}

// ---------------------------------------------------------------- GEMM1 (TF32 tensor core): g_h0 = x @ W1  [50000x128]@[128x128]
// Block tile 64x128, 8 warps (4 M-warps x 2 N-warps), warp tile 16x64 (4 wmma frags).
// 50000 % 16 == 0 -> warp tiles are all-valid or all-invalid; no partial stores.
__global__ __launch_bounds__(256) void k_gemm1(const float* __restrict__ x,
                                               const float* __restrict__ W) {
    __shared__ float As[64][36];     // 64x32 + pad
    __shared__ float Bs[32][132];    // 32x128 + pad
    const int tx   = threadIdx.x;
    const int warp = tx >> 5;
    const int wm   = warp & 3;       // M-warp 0..3
    const int wn   = warp >> 2;      // N-warp 0..1
    const int row0 = blockIdx.x * 64;

    wmma::fragment<wmma::accumulator, 16, 16, 8, float> acc[4];
#pragma unroll
    for (int j = 0; j < 4; j++) wmma::fill_fragment(acc[j], 0.0f);

    for (int k0 = 0; k0 < F_IN; k0 += 32) {
        // stage A: 64x32 = 512 float4, 2 per thread
#pragma unroll
        for (int q = 0; q < 2; q++) {
            int idx = tx + 256 * q;          // 0..511
            int r = idx >> 3;
            int c = (idx & 7) * 4;
            float4 v = make_float4(0.f, 0.f, 0.f, 0.f);
            int grow = row0 + r;
            if (grow < N_NODES) v = *(const float4*)&x[grow * F_IN + k0 + c];
            *(float4*)&As[r][c] = v;
        }
        // stage B: 32x128 = 1024 float4, 4 per thread
#pragma unroll
        for (int q = 0; q < 4; q++) {
            int idx = tx + 256 * q;          // 0..1023
            int r = idx >> 5;
            int c = (idx & 31) * 4;
            *(float4*)&Bs[r][c] = *(const float4*)&W[(k0 + r) * H1 + c];
        }
        __syncthreads();

#pragma unroll
        for (int kk = 0; kk < 32; kk += 8) {
            wmma::fragment<wmma::matrix_a, 16, 16, 8, wmma::precision::tf32, wmma::row_major> af;
            wmma::load_matrix_sync(af, &As[wm * 16][kk], 36);
#pragma unroll
            for (int t = 0; t < af.num_elements; t++) af.x[t] = wmma::__float_to_tf32(af.x[t]);
#pragma unroll
            for (int j = 0; j < 4; j++) {
                wmma::fragment<wmma::matrix_b, 16, 16, 8, wmma::precision::tf32, wmma::row_major> bf;
                wmma::load_matrix_sync(bf, &Bs[kk][wn * 64 + j * 16], 132);
#pragma unroll
                for (int t = 0; t < bf.num_elements; t++) bf.x[t] = wmma::__float_to_tf32(bf.x[t]);
                wmma::mma_sync(acc[j], af, bf, acc[j]);
            }
        }
        __syncthreads();
    }

    int grow = row0 + wm * 16;
    if (grow + 16 <= N_NODES) {
#pragma unroll
        for (int j = 0; j < 4; j++)
            wmma::store_matrix_sync(&g_h0[grow * H1 + wn * 64 + j * 16], acc[j], H1,
                                    wmma::mem_row_major);
    }
}

// ---------------------------------------------------------------- agg1 gather: warp per node, 128 feats (float4/lane)
__global__ __launch_bounds__(256) void k_agg1_gather(const float* __restrict__ b1) {
    int node = (blockIdx.x * blockDim.x + threadIdx.x) >> 5;
    if (node >= N_NODES) return;
    int lane = threadIdx.x & 31;

    float di = g_dinv[node];
    float selfs = di * di;

    float4 acc = *(const float4*)&g_h0[node * H1 + lane * 4];
    float4 bb  = *(const float4*)&b1[lane * 4];
    acc.x = acc.x * selfs + bb.x;
    acc.y = acc.y * selfs + bb.y;
    acc.z = acc.z * selfs + bb.z;
    acc.w = acc.w * selfs + bb.w;

    int s = g_rowptr[node];
    int e = g_rowptr[node + 1];
    for (int k = s; k < e; k++) {
        int src = g_esrc[k];
        float nrm = di * g_dinv[src];
        float4 v = *(const float4*)&g_h0[src * H1 + lane * 4];
        acc.x += v.x * nrm;
        acc.y += v.y * nrm;
        acc.z += v.z * nrm;
        acc.w += v.w * nrm;
    }
    *(float4*)&g_agg1[node * H1 + lane * 4] = acc;
}

// ---------------------------------------------------------------- GEMM2 (TF32): g_h2p = relu(g_agg1) @ W2  [50000x128]@[128x64]
// Block tile 64x64, 8 warps (4 M x 2 N), warp tile 16x32 (2 frags). ReLU fused in A stage.
__global__ __launch_bounds__(256) void k_gemm2(const float* __restrict__ W2) {
    __shared__ float As[64][36];
    __shared__ float Bs[32][68];     // 32x64 + pad
    const int tx   = threadIdx.x;
    const int warp = tx >> 5;
    const int wm   = warp & 3;
    const int wn   = warp >> 2;
    const int row0 = blockIdx.x * 64;

    wmma::fragment<wmma::accumulator, 16, 16, 8, float> acc[2];
#pragma unroll
    for (int j = 0; j < 2; j++) wmma::fill_fragment(acc[j], 0.0f);

    for (int k0 = 0; k0 < H1; k0 += 32) {
#pragma unroll
        for (int q = 0; q < 2; q++) {
            int idx = tx + 256 * q;
            int r = idx >> 3;
            int c = (idx & 7) * 4;
            float4 v = make_float4(0.f, 0.f, 0.f, 0.f);
            int grow = row0 + r;
            if (grow < N_NODES) v = *(const float4*)&g_agg1[grow * H1 + k0 + c];
            As[r][c + 0] = fmaxf(v.x, 0.f);
            As[r][c + 1] = fmaxf(v.y, 0.f);
            As[r][c + 2] = fmaxf(v.z, 0.f);
            As[r][c + 3] = fmaxf(v.w, 0.f);
        }
        // stage B: 32x64 = 512 float4, 2 per thread
#pragma unroll
        for (int q = 0; q < 2; q++) {
            int idx = tx + 256 * q;          // 0..511
            int r = idx >> 4;
            int c = (idx & 15) * 4;
            *(float4*)&Bs[r][c] = *(const float4*)&W2[(k0 + r) * H2 + c];
        }
        __syncthreads();

#pragma unroll
        for (int kk = 0; kk < 32; kk += 8) {
            wmma::fragment<wmma::matrix_a, 16, 16, 8, wmma::precision::tf32, wmma::row_major> af;
            wmma::load_matrix_sync(af, &As[wm * 16][kk], 36);
#pragma unroll
            for (int t = 0; t < af.num_elements; t++) af.x[t] = wmma::__float_to_tf32(af.x[t]);
#pragma unroll
            for (int j = 0; j < 2; j++) {
                wmma::fragment<wmma::matrix_b, 16, 16, 8, wmma::precision::tf32, wmma::row_major> bf;
                wmma::load_matrix_sync(bf, &Bs[kk][wn * 32 + j * 16], 68);
#pragma unroll
                for (int t = 0; t < bf.num_elements; t++) bf.x[t] = wmma::__float_to_tf32(bf.x[t]);
                wmma::mma_sync(acc[j], af, bf, acc[j]);
            }
        }
        __syncthreads();
    }

    int grow = row0 + wm * 16;
    if (grow + 16 <= N_NODES) {
#pragma unroll
        for (int j = 0; j < 2; j++)
            wmma::store_matrix_sync(&g_h2p[grow * H2 + wn * 32 + j * 16], acc[j], H2,
                                    wmma::mem_row_major);
    }
}

// ---------------------------------------------------------------- agg2 gather: half-warp per node, 64 feats (float4/lane16)
__global__ __launch_bounds__(256) void k_agg2_gather(const float* __restrict__ b2) {
    int node = (blockIdx.x * blockDim.x + threadIdx.x) >> 4;
    if (node >= N_NODES) return;
    int lane = threadIdx.x & 15;

    float di = g_dinv[node];
    float selfs = di * di;

    float4 acc = *(const float4*)&g_h2p[node * H2 + lane * 4];
    float4 bb  = *(const float4*)&b2[lane * 4];
    acc.x = acc.x * selfs + bb.x;
    acc.y = acc.y * selfs + bb.y;
    acc.z = acc.z * selfs + bb.z;
    acc.w = acc.w * selfs + bb.w;

    int s = g_rowptr[node];
    int e = g_rowptr[node + 1];
    for (int k = s; k < e; k++) {
        int src = g_esrc[k];
        float nrm = di * g_dinv[src];
        float4 v = *(const float4*)&g_h2p[src * H2 + lane * 4];
        acc.x += v.x * nrm;
        acc.y += v.y * nrm;
        acc.z += v.z * nrm;
        acc.w += v.w * nrm;
    }
    *(float4*)&g_agg2[node * H2 + lane * 4] = acc;
}

// ---------------------------------------------------------------- score: half-warp per edge, dot over 64 dims (float4/lane16)
__global__ __launch_bounds__(256) void k_score(const int* __restrict__ pos,
                                               const int* __restrict__ neg,
                                               float* __restrict__ out) {
    int w = (blockIdx.x * blockDim.x + threadIdx.x) >> 4;
    if (w >= 2 * E_SCORE) return;
    int lane = threadIdx.x & 15;
    int src, dst;
    if (w < E_SCORE) { src = pos[w];            dst = pos[E_SCORE + w]; }
    else             { int e = w - E_SCORE; src = neg[e]; dst = neg[E_SCORE + e]; }
    float4 a = *(const float4*)&g_agg2[src * H2 + lane * 4];
    float4 b = *(const float4*)&g_agg2[dst * H2 + lane * 4];
    float s = a.x * b.x + a.y * b.y + a.z * b.z + a.w * b.w;
#pragma unroll
    for (int o = 8; o; o >>= 1) s += __shfl_xor_sync(0xFFFFFFFFu, s, o);
    if (lane == 0) out[w] = s;
}

// ----------------------------------------------------------------
extern "C" void kernel_launch(void* const* d_in, const int* in_sizes, int n_in,
                              void* d_out, int out_size) {
    const float* x    = (const float*)d_in[0];
    const int*   tr   = (const int*)  d_in[1];   // [2, 600000]
    const int*   pos  = (const int*)  d_in[2];   // [2, 200000]
    const int*   neg  = (const int*)  d_in[3];   // [2, 200000]
    const float* W1   = (const float*)d_in[4];
    const float* b1   = (const float*)d_in[5];
    const float* W2   = (const float*)d_in[6];
    const float* b2   = (const float*)d_in[7];
    float* out = (float*)d_out;

    // CSR build (destination-sorted)
    k_zero_cnt<<<(N_NODES + 255) / 256, 256>>>();
    k_count   <<<(E_TRAIN + 255) / 256, 256>>>(tr);
    k_scan1   <<<NB_SCAN, 256>>>();
    k_scan2   <<<1, 256>>>();
    k_scan3   <<<(N_NODES + 255) / 256, 256>>>();
    k_fill    <<<(E_TRAIN + 255) / 256, 256>>>(tr);

    // Layer 1
    k_gemm1<<<(N_NODES + 63) / 64, 256>>>(x, W1);
    k_agg1_gather<<<(N_NODES * 32 + 255) / 256, 256>>>(b1);

    // Layer 2
    k_gemm2<<<(N_NODES + 63) / 64, 256>>>(W2);
    k_agg2_gather<<<(N_NODES * 16 + 255) / 256, 256>>>(b2);

    // Scores
    k_score<<<(2 * E_SCORE * 16 + 255) / 256, 256>>>(pos, neg, out);
}

// round 9
// speedup vs baseline: 1.2833x; 1.2833x over previous
#include <cuda_runtime.h>
#include <math.h>

#define N_NODES 50000
#define F_IN    128
#define H1      128
#define H2      64
#define E_TRAIN 600000
#define E_SCORE 200000
#define NB_SCAN 196                     // ceil(50000/256)

// Scratch buffers (device globals — no allocation allowed)
__device__ float g_dinv  [N_NODES];
__device__ int   g_cnt   [N_NODES];         // in-degree (no self-loop)
__device__ int   g_rowptr[N_NODES + 1];     // CSR row pointers (by dst)
__device__ int   g_cursor[N_NODES];         // fill cursors
__device__ int   g_bsum  [256];             // scan block sums
__device__ int   g_esrc  [E_TRAIN];         // dst-sorted source indices
__device__ float g_h0    [N_NODES * H1];    // x @ W1
__device__ float g_agg1  [N_NODES * H1];    // layer-1 aggregated (pre-relu)
__device__ float g_h2p   [N_NODES * H2];    // relu(agg1) @ W2
__device__ float g_agg2  [N_NODES * H2];    // layer-2 output h2

// ---------------------------------------------------------------- packed f32x2 helpers
__device__ __forceinline__ void fma2(unsigned long long& d,
                                     unsigned long long a,
                                     unsigned long long b) {
    asm("fma.rn.f32x2 %0, %1, %2, %0;" : "+l"(d) : "l"(a), "l"(b));
}
__device__ __forceinline__ float2 u2f(unsigned long long u) {
    float2 f;
    asm("mov.b64 {%0, %1}, %2;" : "=f"(f.x), "=f"(f.y) : "l"(u));
    return f;
}
__device__ __forceinline__ unsigned long long fdup(float a) {
    unsigned long long u;
    asm("mov.b64 %0, {%1, %1};" : "=l"(u) : "f"(a));
    return u;
}

// ---------------------------------------------------------------- degree/CSR build
__global__ void k_zero_cnt() {
    int i = blockIdx.x * blockDim.x + threadIdx.x;
    if (i < N_NODES) g_cnt[i] = 0;
}

__global__ void k_count(const int* __restrict__ ei) {
    int e = blockIdx.x * blockDim.x + threadIdx.x;
    if (e < E_TRAIN) atomicAdd(&g_cnt[ei[E_TRAIN + e]], 1);   // col = target
}

// Shuffle-based block scan; also emits dinv (fused).
__global__ void k_scan1() {
    __shared__ int wsum[8];
    int t = threadIdx.x;
    int i = blockIdx.x * 256 + t;
    int v = (i < N_NODES) ? g_cnt[i] : 0;
    int s = v;
#pragma unroll
    for (int o = 1; o < 32; o <<= 1) {
        int u = __shfl_up_sync(0xFFFFFFFFu, s, o);
        if ((t & 31) >= o) s += u;
    }
    if ((t & 31) == 31) wsum[t >> 5] = s;
    __syncthreads();
    if (t < 8) {
        int w = wsum[t];
        int e = w;
#pragma unroll
        for (int o = 1; o < 8; o <<= 1) {
            int u = __shfl_up_sync(0xFFu, e, o);
            if (t >= o) e += u;
        }
        wsum[t] = e - w;               // exclusive warp offset
    }
    __syncthreads();
    int incl = s + wsum[t >> 5];
    if (i < N_NODES) {
        g_rowptr[i] = incl - v;        // block-local exclusive
        g_dinv[i]   = rsqrtf((float)(v + 1));
    }
    if (t == 255) g_bsum[blockIdx.x] = incl;
}

// scan3 absorbs scan2: block offset = sum of bsum[0..bid-1] (cheap block reduce).
__global__ void k_scan3() {
    __shared__ int wsum[8];
    __shared__ int total;
    int t   = threadIdx.x;
    int bid = blockIdx.x;
    int v = (t < bid) ? g_bsum[t] : 0;      // bid <= 195 < 256
    int s = v;
#pragma unroll
    for (int o = 16; o; o >>= 1) s += __shfl_xor_sync(0xFFFFFFFFu, s, o);
    if ((t & 31) == 0) wsum[t >> 5] = s;
    __syncthreads();
    if (t == 0) {
        int acc = 0;
#pragma unroll
        for (int w = 0; w < 8; w++) acc += wsum[w];
        total = acc;
    }
    __syncthreads();
    int i = bid * 256 + t;
    if (i < N_NODES) {
        int r = g_rowptr[i] + total;
        g_rowptr[i] = r;
        g_cursor[i] = r;
    }
    if (i == 0) g_rowptr[N_NODES] = E_TRAIN;
}

__global__ void k_fill(const int* __restrict__ ei) {
    int e = blockIdx.x * blockDim.x + threadIdx.x;
    if (e >= E_TRAIN) return;
    int dst = ei[E_TRAIN + e];
    int p = atomicAdd(&g_cursor[dst], 1);
    g_esrc[p] = ei[e];
}

// ---------------------------------------------------------------- GEMM1: g_h0 = x @ W1  [50000x128]@[128x128]
// Block tile 128x128, 256 threads (16 tr x 16 tc), thread tile 8 rows x 8 cols.
// Packed f32x2 FMA: x staged DUPLICATED ((v,v) pairs) so LDS.128 yields broadcast pairs;
// W col-pairs packed for free. Accumulators = u64 col-pairs.
#define XD_STRIDE 264   // 2*128 + 8 pad, 16B-aligned rows
#define WS_STRIDE 136   // 128 + 8 pad
__global__ __launch_bounds__(256) void k_gemm1(const float* __restrict__ x,
                                               const float* __restrict__ W) {
    __shared__ float xdup[16 * XD_STRIDE];
    __shared__ float Ws  [16 * WS_STRIDE];
    const int tx   = threadIdx.x;
    const int tr   = tx >> 4;          // 0..15 -> rows tr*8..+7
    const int tc   = tx & 15;          // 0..15 -> cols tc*8..+7
    const int row0 = blockIdx.x * 128;

    unsigned long long acc[8][4];
#pragma unroll
    for (int r = 0; r < 8; r++)
#pragma unroll
        for (int j = 0; j < 4; j++) acc[r][j] = 0ull;

    for (int k0 = 0; k0 < F_IN; k0 += 16) {
        // stage x duplicated: 128 rows x 16 k -> 512 float4 loads, 2/thread
#pragma unroll
        for (int q = 0; q < 2; q++) {
            int idx = tx + 256 * q;            // 0..511
            int row = idx >> 2;                // 0..127
            int kof = (idx & 3) * 4;
            float4 v = make_float4(0.f, 0.f, 0.f, 0.f);
            int grow = row0 + row;
            if (grow < N_NODES) v = *(const float4*)&x[grow * F_IN + k0 + kof];
            *(unsigned long long*)&xdup[(kof + 0) * XD_STRIDE + 2 * row] = fdup(v.x);
            *(unsigned long long*)&xdup[(kof + 1) * XD_STRIDE + 2 * row] = fdup(v.y);
            *(unsigned long long*)&xdup[(kof + 2) * XD_STRIDE + 2 * row] = fdup(v.z);
            *(unsigned long long*)&xdup[(kof + 3) * XD_STRIDE + 2 * row] = fdup(v.w);
        }
        // stage W: 16x128 = 512 float4, 2/thread, coalesced
#pragma unroll
        for (int q = 0; q < 2; q++) {
            int idx = tx + 256 * q;            // 0..511
            int r = idx >> 5;
            int c = (idx & 31) * 4;
            *(float4*)&Ws[r * WS_STRIDE + c] = *(const float4*)&W[(k0 + r) * H1 + c];
        }
        __syncthreads();

#pragma unroll
        for (int kk = 0; kk < 16; kk++) {
            const ulonglong2* xp = (const ulonglong2*)&xdup[kk * XD_STRIDE + tr * 16];
            unsigned long long xa[8];
#pragma unroll
            for (int i = 0; i < 4; i++) {
                ulonglong2 p = xp[i];
                xa[2 * i + 0] = p.x;
                xa[2 * i + 1] = p.y;
            }
            const ulonglong2* wp = (const ulonglong2*)&Ws[kk * WS_STRIDE + tc * 8];
            ulonglong2 w0 = wp[0], w1 = wp[1];
            unsigned long long wb[4] = { w0.x, w0.y, w1.x, w1.y };
#pragma unroll
            for (int r = 0; r < 8; r++)
#pragma unroll
                for (int j = 0; j < 4; j++)
                    fma2(acc[r][j], xa[r], wb[j]);
        }
        __syncthreads();
    }

#pragma unroll
    for (int r = 0; r < 8; r++) {
        int grow = row0 + tr * 8 + r;
        if (grow < N_NODES) {
            float2 f0 = u2f(acc[r][0]), f1 = u2f(acc[r][1]);
            float2 f2 = u2f(acc[r][2]), f3 = u2f(acc[r][3]);
            float* o = &g_h0[grow * H1 + tc * 8];
            *(float4*)(o + 0) = make_float4(f0.x, f0.y, f1.x, f1.y);
            *(float4*)(o + 4) = make_float4(f2.x, f2.y, f3.x, f3.y);
        }
    }
}

// ---------------------------------------------------------------- agg1 gather: warp per node, 128 feats (float4/lane)
__global__ __launch_bounds__(256) void k_agg1_gather(const float* __restrict__ b1) {
    int node = (blockIdx.x * blockDim.x + threadIdx.x) >> 5;
    if (node >= N_NODES) return;
    int lane = threadIdx.x & 31;

    float di = g_dinv[node];
    float selfs = di * di;

    float4 acc = *(const float4*)&g_h0[node * H1 + lane * 4];
    float4 bb  = *(const float4*)&b1[lane * 4];
    acc.x = acc.x * selfs + bb.x;
    acc.y = acc.y * selfs + bb.y;
    acc.z = acc.z * selfs + bb.z;
    acc.w = acc.w * selfs + bb.w;

    int s = g_rowptr[node];
    int e = g_rowptr[node + 1];
    for (int k = s; k < e; k++) {
        int src = g_esrc[k];
        float nrm = di * g_dinv[src];
        float4 v = *(const float4*)&g_h0[src * H1 + lane * 4];
        acc.x += v.x * nrm;
        acc.y += v.y * nrm;
        acc.z += v.z * nrm;
        acc.w += v.w * nrm;
    }
    *(float4*)&g_agg1[node * H1 + lane * 4] = acc;
}

// ---------------------------------------------------------------- GEMM2: g_h2p = relu(g_agg1) @ W2  [50000x128]@[128x64]
// Block tile 128x64, 256 threads, thread tile 8 rows x 4 cols. ReLU fused in x staging.
#define W2_STRIDE 72   // 64 + 8 pad
__global__ __launch_bounds__(256) void k_gemm2(const float* __restrict__ W2) {
    __shared__ float xdup[16 * XD_STRIDE];
    __shared__ float Ws  [16 * W2_STRIDE];
    const int tx   = threadIdx.x;
    const int tr   = tx >> 4;
    const int tc   = tx & 15;          // cols tc*4..+3
    const int row0 = blockIdx.x * 128;

    unsigned long long acc[8][2];
#pragma unroll
    for (int r = 0; r < 8; r++) {
        acc[r][0] = 0ull; acc[r][1] = 0ull;
    }

    for (int k0 = 0; k0 < H1; k0 += 16) {
#pragma unroll
        for (int q = 0; q < 2; q++) {
            int idx = tx + 256 * q;
            int row = idx >> 2;
            int kof = (idx & 3) * 4;
            float4 v = make_float4(0.f, 0.f, 0.f, 0.f);
            int grow = row0 + row;
            if (grow < N_NODES) v = *(const float4*)&g_agg1[grow * H1 + k0 + kof];
            *(unsigned long long*)&xdup[(kof + 0) * XD_STRIDE + 2 * row] = fdup(fmaxf(v.x, 0.f));
            *(unsigned long long*)&xdup[(kof + 1) * XD_STRIDE + 2 * row] = fdup(fmaxf(v.y, 0.f));
            *(unsigned long long*)&xdup[(kof + 2) * XD_STRIDE + 2 * row] = fdup(fmaxf(v.z, 0.f));
            *(unsigned long long*)&xdup[(kof + 3) * XD_STRIDE + 2 * row] = fdup(fmaxf(v.w, 0.f));
        }
        // stage W2: 16x64 = 256 float4, 1/thread
        {
            int r = tx >> 4;
            int c = (tx & 15) * 4;
            *(float4*)&Ws[r * W2_STRIDE + c] = *(const float4*)&W2[(k0 + r) * H2 + c];
        }
        __syncthreads();

#pragma unroll
        for (int kk = 0; kk < 16; kk++) {
            const ulonglong2* xp = (const ulonglong2*)&xdup[kk * XD_STRIDE + tr * 16];
            unsigned long long xa[8];
#pragma unroll
            for (int i = 0; i < 4; i++) {
                ulonglong2 p = xp[i];
                xa[2 * i + 0] = p.x;
                xa[2 * i + 1] = p.y;
            }
            ulonglong2 w0 = *(const ulonglong2*)&Ws[kk * W2_STRIDE + tc * 4];
            unsigned long long wb0 = w0.x, wb1 = w0.y;
#pragma unroll
            for (int r = 0; r < 8; r++) {
                fma2(acc[r][0], xa[r], wb0);
                fma2(acc[r][1], xa[r], wb1);
            }
        }
        __syncthreads();
    }

#pragma unroll
    for (int r = 0; r < 8; r++) {
        int grow = row0 + tr * 8 + r;
        if (grow < N_NODES) {
            float2 f0 = u2f(acc[r][0]), f1 = u2f(acc[r][1]);
            *(float4*)&g_h2p[grow * H2 + tc * 4] = make_float4(f0.x, f0.y, f1.x, f1.y);
        }
    }
}

// ---------------------------------------------------------------- agg2 gather: half-warp per node, 64 feats (float4/lane16)
__global__ __launch_bounds__(256) void k_agg2_gather(const float* __restrict__ b2) {
    int node = (blockIdx.x * blockDim.x + threadIdx.x) >> 4;
    if (node >= N_NODES) return;
    int lane = threadIdx.x & 15;

    float di = g_dinv[node];
    float selfs = di * di;

    float4 acc = *(const float4*)&g_h2p[node * H2 + lane * 4];
    float4 bb  = *(const float4*)&b2[lane * 4];
    acc.x = acc.x * selfs + bb.x;
    acc.y = acc.y * selfs + bb.y;
    acc.z = acc.z * selfs + bb.z;
    acc.w = acc.w * selfs + bb.w;

    int s = g_rowptr[node];
    int e = g_rowptr[node + 1];
    for (int k = s; k < e; k++) {
        int src = g_esrc[k];
        float nrm = di * g_dinv[src];
        float4 v = *(const float4*)&g_h2p[src * H2 + lane * 4];
        acc.x += v.x * nrm;
        acc.y += v.y * nrm;
        acc.z += v.z * nrm;
        acc.w += v.w * nrm;
    }
    *(float4*)&g_agg2[node * H2 + lane * 4] = acc;
}

// ---------------------------------------------------------------- score: half-warp per edge, dot over 64 dims (float4/lane16)
__global__ __launch_bounds__(256) void k_score(const int* __restrict__ pos,
                                               const int* __restrict__ neg,
                                               float* __restrict__ out) {
    int w = (blockIdx.x * blockDim.x + threadIdx.x) >> 4;
    if (w >= 2 * E_SCORE) return;
    int lane = threadIdx.x & 15;
    int src, dst;
    if (w < E_SCORE) { src = pos[w];            dst = pos[E_SCORE + w]; }
    else             { int e = w - E_SCORE; src = neg[e]; dst = neg[E_SCORE + e]; }
    float4 a = *(const float4*)&g_agg2[src * H2 + lane * 4];
    float4 b = *(const float4*)&g_agg2[dst * H2 + lane * 4];
    float s = a.x * b.x + a.y * b.y + a.z * b.z + a.w * b.w;
#pragma unroll
    for (int o = 8; o; o >>= 1) s += __shfl_xor_sync(0xFFFFFFFFu, s, o);
    if (lane == 0) out[w] = s;
}

// ----------------------------------------------------------------
extern "C" void kernel_launch(void* const* d_in, const int* in_sizes, int n_in,
                              void* d_out, int out_size) {
    const float* x    = (const float*)d_in[0];
    const int*   tr   = (const int*)  d_in[1];   // [2, 600000]
    const int*   pos  = (const int*)  d_in[2];   // [2, 200000]
    const int*   neg  = (const int*)  d_in[3];   // [2, 200000]
    const float* W1   = (const float*)d_in[4];
    const float* b1   = (const float*)d_in[5];
    const float* W2   = (const float*)d_in[6];
    const float* b2   = (const float*)d_in[7];
    float* out = (float*)d_out;

    // CSR build (destination-sorted)
    k_zero_cnt<<<(N_NODES + 255) / 256, 256>>>();
    k_count   <<<(E_TRAIN + 255) / 256, 256>>>(tr);
    k_scan1   <<<NB_SCAN, 256>>>();
    k_scan3   <<<NB_SCAN, 256>>>();
    k_fill    <<<(E_TRAIN + 255) / 256, 256>>>(tr);

    // Layer 1
    k_gemm1<<<(N_NODES + 127) / 128, 256>>>(x, W1);
    k_agg1_gather<<<(N_NODES * 32 + 255) / 256, 256>>>(b1);

    // Layer 2
    k_gemm2<<<(N_NODES + 127) / 128, 256>>>(W2);
    k_agg2_gather<<<(N_NODES * 16 + 255) / 256, 256>>>(b2);

    // Scores
    k_score<<<(2 * E_SCORE * 16 + 255) / 256, 256>>>(pos, neg, out);
}